// round 12
// baseline (speedup 1.0000x reference)
#include <cuda_runtime.h>

#define N_BATCH 4
#define C_CH    256
#define C2      (C_CH / 2)        // 128 float2 lanes
#define H_DIM   96
#define W_DIM   96
#define HW      (H_DIM * W_DIM)
#define OUTS    7
#define BINS    (OUTS * OUTS)     // 49
#define NSAMP   (BINS * 4)        // 196 bilinear samples per roi
#define SPATIAL_SCALE 0.0625f
#define TPB     128               // thread = 2 channels, block = 1 roi
#define K_ROIS  1024

#define SSTR    17                // stage stride (odd -> low STS conflict)
#define NB_A    17
#define NB_B    16
#define NB_C    16

// Scratch: NHWC-transposed features (b, h, w, c)
__device__ float g_featT[(size_t)N_BATCH * HW * C_CH];
// Per-roi sample tables: combined corner offsets (float2 units) + weights*0.25
__device__ int4   g_toff[(size_t)K_ROIS * NSAMP];   // 3.2 MB
__device__ float4 g_tw[(size_t)K_ROIS * NSAMP];     // 3.2 MB

// ---------------------------------------------------------------------------
// Transpose (N, C, HW) -> (N, HW, C), 32x32 smem tile.
// ---------------------------------------------------------------------------
__global__ void nchw_to_nhwc(const float* __restrict__ in) {
    __shared__ float tile[32][33];
    const int n   = blockIdx.z;
    const int hw0 = blockIdx.x * 32;
    const int c0  = blockIdx.y * 32;
    const float* inp = in + (size_t)n * C_CH * HW;
    float* op = g_featT + (size_t)n * HW * C_CH;

    const int x = hw0 + threadIdx.x;
#pragma unroll
    for (int j = 0; j < 32; j += 8) {
        const int cc = c0 + threadIdx.y + j;
        tile[threadIdx.y + j][threadIdx.x] = inp[(size_t)cc * HW + x];
    }
    __syncthreads();
    const int cx = c0 + threadIdx.x;
#pragma unroll
    for (int j = 0; j < 32; j += 8) {
        const int hh = hw0 + threadIdx.y + j;
        op[(size_t)hh * C_CH + cx] = tile[threadIdx.x][threadIdx.y + j];
    }
}

// ---------------------------------------------------------------------------
// 1D interp helper: sample g (0..13) along an axis of length 96.
// Returns lo/hi indices and lo/hi weights (zeroed if invalid).
// ---------------------------------------------------------------------------
__device__ __forceinline__ void interp_axis(float start, float binsz, int g,
                                            int& lo, int& hi, float& wl, float& wh) {
    const float off   = (float)(g >> 1) + 0.25f + 0.5f * (float)(g & 1);
    const float coord = fmaf(binsz, off, start);
    const bool  valid = (coord >= -1.0f) && (coord <= 96.0f);
    const float cc    = fminf(fmaxf(coord, 0.0f), 95.0f);
    const float lof   = floorf(cc);
    lo = (int)lof;
    hi = min(lo + 1, 95);
    const float fr = cc - lof;
    wl = valid ? 1.0f - fr : 0.0f;
    wh = valid ? fr        : 0.0f;
}

// ---------------------------------------------------------------------------
// Table precompute: grid = K rois, 224 threads; thread s computes sample s.
// ---------------------------------------------------------------------------
__global__ __launch_bounds__(224) void build_tables(const float* __restrict__ rois) {
    const int k = blockIdx.x;
    const int s = threadIdx.x;
    if (s >= NSAMP) return;

    const float* r = rois + (size_t)k * 5;
    const int   b  = (int)r[0];
    const float x1 = r[1] * SPATIAL_SCALE;
    const float y1 = r[2] * SPATIAL_SCALE;
    const float x2 = r[3] * SPATIAL_SCALE;
    const float y2 = r[4] * SPATIAL_SCALE;
    const float binw = fmaxf(x2 - x1, 1.0f) * (1.0f / OUTS);
    const float binh = fmaxf(y2 - y1, 1.0f) * (1.0f / OUTS);

    const int bin = s >> 2;
    const int sub = s & 3;
    const int i   = bin / OUTS;
    const int j   = bin - i * OUTS;
    const int gy  = 2 * i + (sub >> 1);
    const int gx  = 2 * j + (sub & 1);

    int ylo, yhi, xlo, xhi; float wyl, wyh, wxl, wxh;
    interp_axis(y1, binh, gy, ylo, yhi, wyl, wyh);
    interp_axis(x1, binw, gx, xlo, xhi, wxl, wxh);

    const int yl = (b * H_DIM + ylo) * W_DIM * C2;
    const int yh = (b * H_DIM + yhi) * W_DIM * C2;
    const int xl = xlo * C2;
    const int xh = xhi * C2;

    g_toff[(size_t)k * NSAMP + s] = make_int4(yl + xl, yl + xh, yh + xl, yh + xh);
    g_tw[(size_t)k * NSAMP + s]   = make_float4(0.25f * wyl * wxl, 0.25f * wyl * wxh,
                                                0.25f * wyh * wxl, 0.25f * wyh * wxh);
}

// ---------------------------------------------------------------------------
// RoI Align main: block = 1 roi, 128 threads, thread = 2 channels.
// Sample tables read via warp-uniform LDG (1 wavefront each, L1-resident),
// keeping the L1/smem pipe for the data gathers. Stage = 17 KB, 3 phases.
// ---------------------------------------------------------------------------
__global__ __launch_bounds__(TPB, 8) void roi_align_kernel(float* __restrict__ out) {
    __shared__ float stage[C_CH * SSTR];             // 17408 B

    const int k   = blockIdx.x;
    const int tid = threadIdx.x;

    const float2* fp = (const float2*)g_featT + tid;   // 2 channels per thread
    const int c0 = 2 * tid;
    float* obase = out + (size_t)k * C_CH * BINS;
    const int4*   toff = g_toff + (size_t)k * NSAMP;
    const float4* tw   = g_tw   + (size_t)k * NSAMP;

#define DO_PHASE(B0, NB)                                                      \
    {                                                                         \
        for (int b = (B0); b < (B0) + (NB); b++) {                            \
            float ax = 0.f, ay = 0.f;                                         \
            _Pragma("unroll")                                                 \
            for (int sub = 0; sub < 4; sub++) {                               \
                const int4   o = __ldg(toff + b * 4 + sub);                   \
                const float4 w = __ldg(tw   + b * 4 + sub);                   \
                const float2 v0 = __ldg(fp + o.x);                            \
                const float2 v1 = __ldg(fp + o.y);                            \
                const float2 v2 = __ldg(fp + o.z);                            \
                const float2 v3 = __ldg(fp + o.w);                            \
                ax += w.x * v0.x + w.y * v1.x + w.z * v2.x + w.w * v3.x;      \
                ay += w.x * v0.y + w.y * v1.y + w.z * v2.y + w.w * v3.y;      \
            }                                                                 \
            stage[(c0    ) * SSTR + (b - (B0))] = ax;                         \
            stage[(c0 + 1) * SSTR + (b - (B0))] = ay;                         \
        }                                                                     \
        __syncthreads();                                                      \
        for (int t = tid; t < C_CH * (NB); t += TPB) {                        \
            const int c  = t / (NB);                                          \
            const int lb = t - c * (NB);                                      \
            obase[c * BINS + (B0) + lb] = stage[c * SSTR + lb];               \
        }                                                                     \
        __syncthreads();                                                      \
    }

    DO_PHASE(0, NB_A)
    DO_PHASE(NB_A, NB_B)
    DO_PHASE(NB_A + NB_B, NB_C)
#undef DO_PHASE
}

extern "C" void kernel_launch(void* const* d_in, const int* in_sizes, int n_in,
                              void* d_out, int out_size) {
    const float* features = (const float*)d_in[0];
    const float* rois     = (const float*)d_in[1];
    float* out            = (float*)d_out;
    const int K = in_sizes[1] / 5;

    // 1) NCHW -> NHWC transpose (independent of tables; overlaps via stream order)
    nchw_to_nhwc<<<dim3(HW / 32, C_CH / 32, N_BATCH), dim3(32, 8)>>>(features);

    // 2) Per-roi sample tables (offsets + folded weights) in global scratch
    build_tables<<<K, 224>>>(rois);

    // 3) RoI Align gather; tables via uniform LDG, data via float2 LDG
    roi_align_kernel<<<K, TPB>>>(out);
}